// round 15
// baseline (speedup 1.0000x reference)
#include <cuda_runtime.h>
#include <cuda_fp16.h>
#include <math.h>
#include <stdint.h>

// Problem constants
#define Dd 256
#define Hh 8
#define DHh 32
#define Pmax 128
#define Bmax 16
#define Nmax 6000
#define FF 1024

// ---------------- scratch (static __device__ — no allocation allowed) ----------
__device__ __half d_q16[Nmax * Dd];                     // q projection fp16
__device__ __half d_k16[Pmax * Dd];
__device__ float  d_v[Pmax * Dd];
__device__ float  d_scores[(size_t)Nmax * Hh * Pmax];
__device__ __half d_x16[(size_t)Bmax * Nmax * Dd];      // post-LN1 (fp16)
__device__ __half d_ctx16[(size_t)Bmax * Nmax * Dd];    // attention context fp16
__device__ __half d_hidden16[(size_t)Bmax * Nmax * FF]; // FFN hidden fp16
__device__ __half d_hg16[Nmax * Dd];                    // H_genes fp16
__device__ __half d_wq16[Dd * Dd];
__device__ __half d_wo16[Dd * Dd];
__device__ __half d_w116[FF * Dd];
__device__ __half d_w216[Dd * FF];
__device__ int    d_segs[2 * Bmax];
__device__ int    d_hasany[Bmax];

// ---------------- helpers -------------------------------------------------------
__device__ __forceinline__ uint32_t smem_u32(const void* p) {
    uint32_t a;
    asm("{ .reg .u64 t; cvta.to.shared.u64 t, %1; cvt.u32.u64 %0, t; }" : "=r"(a) : "l"(p));
    return a;
}

// fast GELU: 0.5x(1+tanh(sqrt(2/pi)(x + 0.044715 x^3))), tanh.approx MUFU
__device__ __forceinline__ float fast_gelu(float x) {
    float x2 = x * x;
    float u = x * fmaf(0.0356774081f, x2, 0.7978845608f);
    float t;
    asm("tanh.approx.f32 %0, %1;" : "=f"(t) : "f"(u));
    float hx = 0.5f * x;
    return fmaf(hx, t, hx);
}

#define LDSM4(R0, R1, R2, R3, ADDR)                                               \
    asm volatile("ldmatrix.sync.aligned.m8n8.x4.shared.b16 {%0,%1,%2,%3}, [%4];"  \
        : "=r"(R0), "=r"(R1), "=r"(R2), "=r"(R3) : "r"(ADDR))

#define MMA_F16(d, A0, A1, A2, A3, B0, B1)                                        \
    asm volatile("mma.sync.aligned.m16n8k16.row.col.f32.f16.f16.f32 "             \
        "{%0,%1,%2,%3},{%4,%5,%6,%7},{%8,%9},{%0,%1,%2,%3};"                      \
        : "+f"((d)[0]), "+f"((d)[1]), "+f"((d)[2]), "+f"((d)[3])                   \
        : "r"(A0), "r"(A1), "r"(A2), "r"(A3), "r"(B0), "r"(B1))

// ---------------- single fused fp32 -> fp16 conversion ---------------------------
#define HG4 (Nmax * Dd / 4)
#define WQ4 (Dd * Dd / 4)
#define W14 (FF * Dd / 4)
__global__ void f2h_all(const float* __restrict__ Hg, const float* __restrict__ ipw,
                        const float* __restrict__ opw, const float* __restrict__ w1,
                        const float* __restrict__ w2) {
    int i = blockIdx.x * blockDim.x + threadIdx.x;
    const float* src; __half* dst; int off;
    if (i < HG4)                       { src = Hg;  dst = d_hg16; off = i; }
    else if (i < HG4 + WQ4)            { src = ipw; dst = d_wq16; off = i - HG4; }
    else if (i < HG4 + 2*WQ4)          { src = opw; dst = d_wo16; off = i - HG4 - WQ4; }
    else if (i < HG4 + 2*WQ4 + W14)    { src = w1;  dst = d_w116; off = i - HG4 - 2*WQ4; }
    else if (i < HG4 + 2*WQ4 + 2*W14)  { src = w2;  dst = d_w216; off = i - HG4 - 2*WQ4 - W14; }
    else return;
    float4 v = *(const float4*)(src + off * 4);
    __half2* d2 = (__half2*)(dst + off * 4);
    d2[0] = __floats2half2_rn(v.x, v.y);
    d2[1] = __floats2half2_rn(v.z, v.w);
}

// ======================= fp16 tensor-core GEMM (cp.async + ldmatrix) ============
// C[m,n] = sum_k A[m,k]*B[n,k] + bias[n]   (A, B fp16; accum fp32)
// MODE 0: C fp32   MODE 1: fast gelu -> C16   MODE 5: plain -> C16
// MODE 3: LN1 fused: v = res[m%Nrows] + hasany*(acc+bias); LN -> C16 fp16
// MODE 4: LN2 fused: v = acc + bias + res16[m];            LN -> C fp32
// Block tile 128(M) x 256(N); 16 warps, warp 64x32; K-chunk 64 fp16; 3 stages.
// KT is the compile-time K so nch and all buffer addressing fold to constants.
#define SMEM_SZ 147456

template <int MODE, int KT>
__global__ __launch_bounds__(512, 1) void tgemm(
    const __half* __restrict__ A, const __half* __restrict__ B,
    const float* __restrict__ bias, const float* __restrict__ res,
    const __half* __restrict__ res16,
    float* __restrict__ C, __half* __restrict__ C16,
    const float* __restrict__ lg, const float* __restrict__ lb,
    int M, int Nn, int Nrows)
{
    extern __shared__ __align__(128) float sm[];
    uint32_t sbase = smem_u32(sm);
    int tid = threadIdx.x, wid = tid >> 5, lane = tid & 31;
    int m0 = blockIdx.y * 128, n0 = blockIdx.x * 256;
    int wm = wid & 1, wn = wid >> 1;
    constexpr int nch = KT >> 6;

    auto issue_stage = [&](int c) {
        int k0 = c << 6, buf = c % 3;
        uint32_t sa = sbase + (uint32_t)buf * 16384u;
        uint32_t sb = sbase + 49152u + (uint32_t)buf * 32768u;
#pragma unroll
        for (int j = 0; j < 2; j++) {
            int seg = tid + j * 512;
            int r = seg >> 3, kk = (seg & 7) << 3;
            uint32_t off = ((uint32_t)(r * 128 + kk * 2)) ^ ((uint32_t)(r & 7) << 4);
            int arow = m0 + r;
            const __half* gA = A + (size_t)(arow < M ? arow : M - 1) * KT + k0 + kk;
            int szA = (arow < M) ? 16 : 0;
            asm volatile("cp.async.cg.shared.global [%0], [%1], 16, %2;"
                         :: "r"(sa + off), "l"(gA), "r"(szA));
        }
#pragma unroll
        for (int j = 0; j < 4; j++) {
            int seg = tid + j * 512;
            int r = seg >> 3, kk = (seg & 7) << 3;
            uint32_t off = ((uint32_t)(r * 128 + kk * 2)) ^ ((uint32_t)(r & 7) << 4);
            const __half* gB = B + (size_t)(n0 + r) * KT + k0 + kk;
            asm volatile("cp.async.cg.shared.global [%0], [%1], 16;"
                         :: "r"(sb + off), "l"(gB));
        }
        asm volatile("cp.async.commit_group;" ::: "memory");
    };

    float acc[16][4] = {};

    int a_mloc = lane & 15;
    int a_kb   = (lane >> 4) << 4;
    int b_nloc = (((lane >> 4) & 1) << 3) + (lane & 7);
    int b_kb   = ((lane >> 3) & 1) << 4;

    auto compute = [&](int buf) {
        uint32_t sa = sbase + (uint32_t)buf * 16384u;
        uint32_t sb = sbase + 49152u + (uint32_t)buf * 32768u;
#pragma unroll
        for (int ks = 0; ks < 4; ks++) {
            int kb = ks * 32;
            uint32_t af[4][4];
#pragma unroll
            for (int i = 0; i < 4; i++) {
                int row = wm * 64 + i * 16 + a_mloc;
                uint32_t off = ((uint32_t)(row * 128 + kb + a_kb)) ^ ((uint32_t)(row & 7) << 4);
                LDSM4(af[i][0], af[i][1], af[i][2], af[i][3], sa + off);
            }
            uint32_t bf[4][2];
#pragma unroll
            for (int jj = 0; jj < 2; jj++) {
                int row = wn * 32 + jj * 16 + b_nloc;
                uint32_t off = ((uint32_t)(row * 128 + kb + b_kb)) ^ ((uint32_t)(row & 7) << 4);
                uint32_t r0, r1, r2, r3;
                LDSM4(r0, r1, r2, r3, sb + off);
                bf[jj * 2][0] = r0; bf[jj * 2][1] = r1;
                bf[jj * 2 + 1][0] = r2; bf[jj * 2 + 1][1] = r3;
            }
#pragma unroll
            for (int i = 0; i < 4; i++)
#pragma unroll
                for (int j = 0; j < 4; j++)
                    MMA_F16(acc[i * 4 + j], af[i][0], af[i][1], af[i][2], af[i][3],
                            bf[j][0], bf[j][1]);
        }
    };

    issue_stage(0);
    if (nch > 1) issue_stage(1);
    else asm volatile("cp.async.commit_group;" ::: "memory");
#pragma unroll 2
    for (int c = 0; c < nch; c++) {
        asm volatile("cp.async.wait_group 1;" ::: "memory");
        __syncthreads();
        if (c + 2 < nch) issue_stage(c + 2);
        else asm volatile("cp.async.commit_group;" ::: "memory");
        compute(c % 3);
    }

    int g = lane >> 2, q4 = lane & 3;

    if (MODE == 0 || MODE == 1 || MODE == 5) {
#pragma unroll
        for (int i = 0; i < 4; i++) {
#pragma unroll
            for (int j = 0; j < 4; j++) {
                int col = n0 + wn * 32 + j * 8 + q4 * 2;
                float b0 = bias[col], b1 = bias[col + 1];
                const float* a4 = acc[i * 4 + j];
#pragma unroll
                for (int half = 0; half < 2; half++) {
                    int mrow = m0 + wm * 64 + i * 16 + g + half * 8;
                    if (mrow >= M) continue;
                    float v0 = a4[half * 2 + 0] + b0;
                    float v1 = a4[half * 2 + 1] + b1;
                    if (MODE == 1) {
                        v0 = fast_gelu(v0);
                        v1 = fast_gelu(v1);
                    }
                    if (MODE == 1 || MODE == 5)
                        *(__half2*)(C16 + (size_t)mrow * Nn + col) = __floats2half2_rn(v0, v1);
                    else
                        *(float2*)(C + (size_t)mrow * Nn + col) = make_float2(v0, v1);
                }
            }
        }
    } else {
        asm volatile("cp.async.wait_group 0;" ::: "memory");
        __syncthreads();
        float* sv = sm;
#pragma unroll
        for (int i = 0; i < 4; i++) {
#pragma unroll
            for (int j = 0; j < 4; j++) {
                int col = wn * 32 + j * 8 + q4 * 2;
                float b0 = bias[col], b1 = bias[col + 1];
                const float* a4 = acc[i * 4 + j];
#pragma unroll
                for (int half = 0; half < 2; half++) {
                    int lr = wm * 64 + i * 16 + g + half * 8;
                    sv[lr * 264 + col]     = a4[half * 2 + 0] + b0;
                    sv[lr * 264 + col + 1] = a4[half * 2 + 1] + b1;
                }
            }
        }
        __syncthreads();
        int lr0 = wid * 8;
#pragma unroll
        for (int rr = 0; rr < 8; rr++) {
            int lr = lr0 + rr;
            size_t m = (size_t)m0 + lr;
            float vals[8];
            if (MODE == 3) {
                int b = (int)(m / Nrows), n = (int)(m % Nrows);
                float ha = d_hasany[b] ? 1.f : 0.f;
#pragma unroll
                for (int jj = 0; jj < 8; jj++) {
                    int e = lane + 32 * jj;
                    vals[jj] = res[(size_t)n * 256 + e] + ha * sv[lr * 264 + e];
                }
            } else {
#pragma unroll
                for (int jj = 0; jj < 8; jj++) {
                    int e = lane + 32 * jj;
                    vals[jj] = sv[lr * 264 + e] + __half2float(res16[m * 256 + e]);
                }
            }
            float sum = 0.f;
#pragma unroll
            for (int jj = 0; jj < 8; jj++) sum += vals[jj];
#pragma unroll
            for (int o = 16; o; o >>= 1) sum += __shfl_xor_sync(0xffffffffu, sum, o);
            float mu = sum * (1.f / 256.f);
            float s2 = 0.f;
#pragma unroll
            for (int jj = 0; jj < 8; jj++) { float dd = vals[jj] - mu; s2 += dd * dd; }
#pragma unroll
            for (int o = 16; o; o >>= 1) s2 += __shfl_xor_sync(0xffffffffu, s2, o);
            float rs = rsqrtf(s2 * (1.f / 256.f) + 1e-5f);
#pragma unroll
            for (int jj = 0; jj < 8; jj++) {
                int e = lane + 32 * jj;
                float ov = (vals[jj] - mu) * rs * lg[e] + lb[e];
                if (MODE == 3) C16[m * 256 + e] = __float2half(ov);
                else           C[m * 256 + e] = ov;
            }
        }
    }
}

// ---------------- k/v projection + segment scan (merged) ------------------------
__global__ void kv_kernel(const float* __restrict__ Hg, const int* __restrict__ idx,
                          const float* __restrict__ ipw, const float* __restrict__ ipb,
                          const int* __restrict__ ba, int P, int B) {
    __shared__ float hrow[Dd];
    int p = blockIdx.x, t = threadIdx.x;
    if (p == 0 && t == 0) {
        for (int b = 0; b < B; b++) {
            int s = P, e = 0;
            for (int pp = 0; pp < P; pp++)
                if (ba[pp] == b) { if (pp < s) s = pp; e = pp + 1; }
            if (e > s) { d_segs[2*b] = s; d_segs[2*b+1] = e; d_hasany[b] = 1; }
            else       { d_segs[2*b] = 0; d_segs[2*b+1] = 0; d_hasany[b] = 0; }
        }
    }
    hrow[t] = Hg[(size_t)idx[p] * Dd + t];
    __syncthreads();
    const float4* h4 = (const float4*)hrow;
    const float4* wk = (const float4*)(ipw + (size_t)(Dd + t) * Dd);
    const float4* wv = (const float4*)(ipw + (size_t)(2 * Dd + t) * Dd);
    float ak = ipb[Dd + t], av = ipb[2 * Dd + t];
#pragma unroll 16
    for (int c = 0; c < Dd / 4; c++) {
        float4 hv = h4[c]; float4 a = wk[c]; float4 b = wv[c];
        ak += hv.x*a.x + hv.y*a.y + hv.z*a.z + hv.w*a.w;
        av += hv.x*b.x + hv.y*b.y + hv.z*b.z + hv.w*b.w;
    }
    d_k16[p * Dd + t] = __float2half(ak);
    d_v[p * Dd + t]   = av;
}

// ---------------- tensor-core scores: C_h[n,p] = scale * q_h @ k_h^T -----------
// grid (ceil(N/128), 8 heads); block 256 = 8 warps, warp tile 16n x 128p
__global__ __launch_bounds__(256, 1) void scores_mma(int N) {
    __shared__ __align__(128) char smem[32768];  // q 16KB | k 16KB, 128B rows
    uint32_t sbase = smem_u32(smem);
    int h = blockIdx.y;
    int n0 = blockIdx.x * 128;
    int tid = threadIdx.x, wid = tid >> 5, lane = tid & 31;

    // load q/k tiles (64B of data per 128B row, swizzled)
#pragma unroll
    for (int j = 0; j < 2; j++) {
        int seg = tid + j * 256;
        int r = seg >> 2, kk = seg & 3;
        uint32_t off = ((uint32_t)(r * 128 + kk * 16)) ^ ((uint32_t)(r & 7) << 4);
        const __half* gq = d_q16 + (size_t)((n0 + r < N) ? n0 + r : 0) * Dd + h * DHh + kk * 8;
        int szq = (n0 + r < N) ? 16 : 0;
        asm volatile("cp.async.cg.shared.global [%0], [%1], 16, %2;"
                     :: "r"(sbase + off), "l"(gq), "r"(szq));
        const __half* gk = d_k16 + (size_t)r * Dd + h * DHh + kk * 8;
        asm volatile("cp.async.cg.shared.global [%0], [%1], 16;"
                     :: "r"(sbase + 16384u + off), "l"(gk));
    }
    asm volatile("cp.async.commit_group;" ::: "memory");
    asm volatile("cp.async.wait_group 0;" ::: "memory");
    __syncthreads();

    int a_mloc = lane & 15;
    int a_kb   = (lane >> 4) << 4;
    int b_nloc = (((lane >> 4) & 1) << 3) + (lane & 7);
    int b_kb   = ((lane >> 3) & 1) << 4;

    float acc[16][4] = {};
#pragma unroll
    for (int ks = 0; ks < 2; ks++) {
        int kb = ks * 32;
        uint32_t a0, a1, a2, a3;
        {
            int row = wid * 16 + a_mloc;
            uint32_t off = ((uint32_t)(row * 128 + kb + a_kb)) ^ ((uint32_t)(row & 7) << 4);
            LDSM4(a0, a1, a2, a3, sbase + off);
        }
#pragma unroll
        for (int jj = 0; jj < 8; jj++) {
            int row = jj * 16 + b_nloc;
            uint32_t off = ((uint32_t)(row * 128 + kb + b_kb)) ^ ((uint32_t)(row & 7) << 4);
            uint32_t r0, r1, r2, r3;
            LDSM4(r0, r1, r2, r3, sbase + 16384u + off);
            MMA_F16(acc[jj * 2 + 0], a0, a1, a2, a3, r0, r1);
            MMA_F16(acc[jj * 2 + 1], a0, a1, a2, a3, r2, r3);
        }
    }

    const float scale = 0.17677669529663687f;  // 1/sqrt(32)
    int g = lane >> 2, q4 = lane & 3;
#pragma unroll
    for (int j = 0; j < 16; j++) {
        int col = j * 8 + q4 * 2;
#pragma unroll
        for (int half = 0; half < 2; half++) {
            int n = n0 + wid * 16 + g + half * 8;
            if (n >= N) continue;
            float* sp = d_scores + ((size_t)n * Hh + h) * Pmax + col;
            *(float2*)sp = make_float2(acc[j][half * 2] * scale,
                                       acc[j][half * 2 + 1] * scale);
        }
    }
}

// ---------------- segment softmax + ctx accumulation (fp16 out) ----------------
__global__ void attn_kernel(int N) {
    int b = blockIdx.y;
    int h = threadIdx.x >> 5, l = threadIdx.x & 31;
    int s = d_segs[2 * b], e = d_segs[2 * b + 1];
    int L = e - s;
    __shared__ float ws[8][128];
    int nEnd = min(N, (int)(blockIdx.x + 1) * 16);
    for (int n = blockIdx.x * 16; n < nEnd; n++) {
        size_t obase = ((size_t)b * N + n) * Dd + h * DHh;
        if (L <= 0) { d_ctx16[obase + l] = __float2half(0.f); continue; }
        float sc[4]; int cnt = 0;
        float m = -1e30f;
        for (int pl = l; pl < L; pl += 32) {
            float xv = d_scores[((size_t)n * Hh + h) * Pmax + s + pl];
            sc[cnt++] = xv;
            m = fmaxf(m, xv);
        }
#pragma unroll
        for (int o = 16; o; o >>= 1) m = fmaxf(m, __shfl_xor_sync(0xffffffffu, m, o));
        float sum = 0.f; cnt = 0;
        for (int pl = l; pl < L; pl += 32) {
            float w = __expf(sc[cnt++] - m);
            ws[h][pl] = w;
            sum += w;
        }
#pragma unroll
        for (int o = 16; o; o >>= 1) sum += __shfl_xor_sync(0xffffffffu, sum, o);
        float inv = 1.f / sum;
        __syncwarp();
        float acc = 0.f;
        for (int pl = 0; pl < L; pl++)
            acc += ws[h][pl] * d_v[(size_t)(s + pl) * Dd + h * DHh + l];
        d_ctx16[obase + l] = __float2half(acc * inv);
        __syncwarp();
    }
}

// -------------------------------- launch ---------------------------------------
extern "C" void kernel_launch(void* const* d_in, const int* in_sizes, int n_in,
                              void* d_out, int out_size) {
    const float* Hg  = (const float*)d_in[0];
    const int*  pidx = (const int*)d_in[1];
    const int*  ba   = (const int*)d_in[2];
    const float* ipw = (const float*)d_in[4];
    const float* ipb = (const float*)d_in[5];
    const float* opw = (const float*)d_in[6];
    const float* opb = (const float*)d_in[7];
    const float* w1  = (const float*)d_in[8];
    const float* b1  = (const float*)d_in[9];
    const float* w2  = (const float*)d_in[10];
    const float* b2  = (const float*)d_in[11];
    const float* g1  = (const float*)d_in[12];
    const float* be1 = (const float*)d_in[13];
    const float* g2  = (const float*)d_in[14];
    const float* be2 = (const float*)d_in[15];
    float* out = (float*)d_out;

    int N = in_sizes[0] / Dd;          // 6000
    int P = in_sizes[1];               // 128
    int B = out_size / (N * Dd);       // 16
    int M = B * N;                     // 96000

    __half *hg16, *wq16, *wo16, *w116, *w216, *x16, *ctx16, *hidden16, *q16;
    cudaGetSymbolAddress((void**)&q16,      d_q16);
    cudaGetSymbolAddress((void**)&hg16,     d_hg16);
    cudaGetSymbolAddress((void**)&wq16,     d_wq16);
    cudaGetSymbolAddress((void**)&wo16,     d_wo16);
    cudaGetSymbolAddress((void**)&w116,     d_w116);
    cudaGetSymbolAddress((void**)&w216,     d_w216);
    cudaGetSymbolAddress((void**)&x16,      d_x16);
    cudaGetSymbolAddress((void**)&ctx16,    d_ctx16);
    cudaGetSymbolAddress((void**)&hidden16, d_hidden16);

    cudaFuncSetAttribute((tgemm<5, 256>),  cudaFuncAttributeMaxDynamicSharedMemorySize, SMEM_SZ);
    cudaFuncSetAttribute((tgemm<1, 256>),  cudaFuncAttributeMaxDynamicSharedMemorySize, SMEM_SZ);
    cudaFuncSetAttribute((tgemm<3, 256>),  cudaFuncAttributeMaxDynamicSharedMemorySize, SMEM_SZ);
    cudaFuncSetAttribute((tgemm<4, 1024>), cudaFuncAttributeMaxDynamicSharedMemorySize, SMEM_SZ);

    int tot4 = HG4 + 2 * WQ4 + 2 * W14;
    // 1. single fused fp16 conversion
    f2h_all<<<(tot4 + 255) / 256, 256>>>(Hg, ipw, opw, w1, w2);
    // 2. k/v projections (k16) + batch segments
    kv_kernel<<<P, Dd>>>(Hg, pidx, ipw, ipb, ba, P, B);
    // 3. q16 = fp16(H @ Wq^T + bq)
    tgemm<5, 256><<<dim3(1, (N + 127) / 128), 512, SMEM_SZ>>>(
        hg16, wq16, ipb, nullptr, nullptr, nullptr, q16, nullptr, nullptr, N, Dd, N);
    // 4. tensor-core scores (shared across batches)
    scores_mma<<<dim3((N + 127) / 128, Hh), 256>>>(N);
    // 5. segment softmax + ctx (fp16 out)
    attn_kernel<<<dim3((N + 15) / 16, B), 256>>>(N);
    // 6. x16 = LN1(H + has_any*(ctx @ Wout^T + bout))
    tgemm<3, 256><<<dim3(1, M / 128), 512, SMEM_SZ>>>(
        ctx16, wo16, opb, Hg, nullptr, nullptr, x16, g1, be1, M, Dd, N);
    // 7. hidden = fast_gelu(x @ W1^T + b1) -> fp16
    tgemm<1, 256><<<dim3(FF / 256, M / 128), 512, SMEM_SZ>>>(
        x16, w116, b1, nullptr, nullptr, nullptr, hidden16, nullptr, nullptr, M, FF, N);
    // 8. out = LN2(x16 + hidden @ W2^T + b2)
    tgemm<4, 1024><<<dim3(1, M / 128), 512, SMEM_SZ>>>(
        hidden16, w216, b2, nullptr, x16, out, nullptr, g2, be2, M, Dd, N);
}

// round 16
// speedup vs baseline: 1.0296x; 1.0296x over previous
#include <cuda_runtime.h>
#include <cuda_fp16.h>
#include <math.h>
#include <stdint.h>

// Problem constants
#define Dd 256
#define Hh 8
#define DHh 32
#define Pmax 128
#define Bmax 16
#define Nmax 6000
#define FF 1024

// ---------------- scratch (static __device__ — no allocation allowed) ----------
__device__ __half d_q16[Nmax * Dd];                     // q projection fp16
__device__ __half d_k16[Pmax * Dd];
__device__ float  d_v[Pmax * Dd];
__device__ float  d_scores[(size_t)Nmax * Hh * Pmax];
__device__ __half d_x16[(size_t)Bmax * Nmax * Dd];      // post-LN1 (fp16)
__device__ __half d_ctx16[(size_t)Bmax * Nmax * Dd];    // attention context fp16
__device__ __half d_hidden16[(size_t)Bmax * Nmax * FF]; // FFN hidden fp16
__device__ __half d_hg16[Nmax * Dd];                    // H_genes fp16
__device__ __half d_wq16[Dd * Dd];
__device__ __half d_wo16[Dd * Dd];
__device__ __half d_w116[FF * Dd];
__device__ __half d_w216[Dd * FF];
__device__ int    d_segs[2 * Bmax];
__device__ int    d_hasany[Bmax];

// ---------------- helpers -------------------------------------------------------
__device__ __forceinline__ uint32_t smem_u32(const void* p) {
    uint32_t a;
    asm("{ .reg .u64 t; cvta.to.shared.u64 t, %1; cvt.u32.u64 %0, t; }" : "=r"(a) : "l"(p));
    return a;
}

// fast GELU: 0.5x(1+tanh(sqrt(2/pi)(x + 0.044715 x^3))), tanh.approx MUFU
__device__ __forceinline__ float fast_gelu(float x) {
    float x2 = x * x;
    float u = x * fmaf(0.0356774081f, x2, 0.7978845608f);
    float t;
    asm("tanh.approx.f32 %0, %1;" : "=f"(t) : "f"(u));
    float hx = 0.5f * x;
    return fmaf(hx, t, hx);
}

#define LDSM4(R0, R1, R2, R3, ADDR)                                               \
    asm volatile("ldmatrix.sync.aligned.m8n8.x4.shared.b16 {%0,%1,%2,%3}, [%4];"  \
        : "=r"(R0), "=r"(R1), "=r"(R2), "=r"(R3) : "r"(ADDR))

#define MMA_F16(d, A0, A1, A2, A3, B0, B1)                                        \
    asm volatile("mma.sync.aligned.m16n8k16.row.col.f32.f16.f16.f32 "             \
        "{%0,%1,%2,%3},{%4,%5,%6,%7},{%8,%9},{%0,%1,%2,%3};"                      \
        : "+f"((d)[0]), "+f"((d)[1]), "+f"((d)[2]), "+f"((d)[3])                   \
        : "r"(A0), "r"(A1), "r"(A2), "r"(A3), "r"(B0), "r"(B1))

// ---------------- single fused fp32 -> fp16 conversion ---------------------------
#define HG4 (Nmax * Dd / 4)
#define WQ4 (Dd * Dd / 4)
#define W14 (FF * Dd / 4)
__global__ void f2h_all(const float* __restrict__ Hg, const float* __restrict__ ipw,
                        const float* __restrict__ opw, const float* __restrict__ w1,
                        const float* __restrict__ w2) {
    int i = blockIdx.x * blockDim.x + threadIdx.x;
    const float* src; __half* dst; int off;
    if (i < HG4)                       { src = Hg;  dst = d_hg16; off = i; }
    else if (i < HG4 + WQ4)            { src = ipw; dst = d_wq16; off = i - HG4; }
    else if (i < HG4 + 2*WQ4)          { src = opw; dst = d_wo16; off = i - HG4 - WQ4; }
    else if (i < HG4 + 2*WQ4 + W14)    { src = w1;  dst = d_w116; off = i - HG4 - 2*WQ4; }
    else if (i < HG4 + 2*WQ4 + 2*W14)  { src = w2;  dst = d_w216; off = i - HG4 - 2*WQ4 - W14; }
    else return;
    float4 v = *(const float4*)(src + off * 4);
    __half2* d2 = (__half2*)(dst + off * 4);
    d2[0] = __floats2half2_rn(v.x, v.y);
    d2[1] = __floats2half2_rn(v.z, v.w);
}

// ======================= fp16 tensor-core GEMM (cp.async + ldmatrix) ============
// C[m,n] = sum_k A[m,k]*B[n,k] + bias[n]   (A, B fp16; accum fp32)
// MODE 0: C fp32   MODE 1: fast gelu -> C16   MODE 5: plain -> C16
// MODE 3: LN1 fused: v = res[m%Nrows] + hasany*(acc+bias); LN -> C16 fp16
// MODE 4: LN2 fused: v = acc + bias + res16[m];            LN -> C fp32
// Block tile 128(M) x 256(N); 16 warps, warp 64x32; K-chunk 64 fp16; 4 stages.
// Smem: A stage s @ s*16KB (64KB), B stage s @ 64KB + s*32KB (128KB) = 192KB.
#define SMEM_SZ 196608

template <int MODE, int KT>
__global__ __launch_bounds__(512, 1) void tgemm(
    const __half* __restrict__ A, const __half* __restrict__ B,
    const float* __restrict__ bias, const float* __restrict__ res,
    const __half* __restrict__ res16,
    float* __restrict__ C, __half* __restrict__ C16,
    const float* __restrict__ lg, const float* __restrict__ lb,
    int M, int Nn, int Nrows)
{
    extern __shared__ __align__(128) float sm[];
    uint32_t sbase = smem_u32(sm);
    int tid = threadIdx.x, wid = tid >> 5, lane = tid & 31;
    int m0 = blockIdx.y * 128, n0 = blockIdx.x * 256;
    int wm = wid & 1, wn = wid >> 1;
    constexpr int nch = KT >> 6;

    auto issue_stage = [&](int c) {
        int k0 = c << 6, buf = c & 3;
        uint32_t sa = sbase + (uint32_t)buf * 16384u;
        uint32_t sb = sbase + 65536u + (uint32_t)buf * 32768u;
#pragma unroll
        for (int j = 0; j < 2; j++) {
            int seg = tid + j * 512;
            int r = seg >> 3, kk = (seg & 7) << 3;
            uint32_t off = ((uint32_t)(r * 128 + kk * 2)) ^ ((uint32_t)(r & 7) << 4);
            int arow = m0 + r;
            const __half* gA = A + (size_t)(arow < M ? arow : M - 1) * KT + k0 + kk;
            int szA = (arow < M) ? 16 : 0;
            asm volatile("cp.async.cg.shared.global [%0], [%1], 16, %2;"
                         :: "r"(sa + off), "l"(gA), "r"(szA));
        }
#pragma unroll
        for (int j = 0; j < 4; j++) {
            int seg = tid + j * 512;
            int r = seg >> 3, kk = (seg & 7) << 3;
            uint32_t off = ((uint32_t)(r * 128 + kk * 2)) ^ ((uint32_t)(r & 7) << 4);
            const __half* gB = B + (size_t)(n0 + r) * KT + k0 + kk;
            asm volatile("cp.async.cg.shared.global [%0], [%1], 16;"
                         :: "r"(sb + off), "l"(gB));
        }
        asm volatile("cp.async.commit_group;" ::: "memory");
    };

    float acc[16][4] = {};

    int a_mloc = lane & 15;
    int a_kb   = (lane >> 4) << 4;
    int b_nloc = (((lane >> 4) & 1) << 3) + (lane & 7);
    int b_kb   = ((lane >> 3) & 1) << 4;

    auto compute = [&](int buf) {
        uint32_t sa = sbase + (uint32_t)buf * 16384u;
        uint32_t sb = sbase + 65536u + (uint32_t)buf * 32768u;
#pragma unroll
        for (int ks = 0; ks < 4; ks++) {
            int kb = ks * 32;
            uint32_t af[4][4];
#pragma unroll
            for (int i = 0; i < 4; i++) {
                int row = wm * 64 + i * 16 + a_mloc;
                uint32_t off = ((uint32_t)(row * 128 + kb + a_kb)) ^ ((uint32_t)(row & 7) << 4);
                LDSM4(af[i][0], af[i][1], af[i][2], af[i][3], sa + off);
            }
            uint32_t bf[4][2];
#pragma unroll
            for (int jj = 0; jj < 2; jj++) {
                int row = wn * 32 + jj * 16 + b_nloc;
                uint32_t off = ((uint32_t)(row * 128 + kb + b_kb)) ^ ((uint32_t)(row & 7) << 4);
                uint32_t r0, r1, r2, r3;
                LDSM4(r0, r1, r2, r3, sb + off);
                bf[jj * 2][0] = r0; bf[jj * 2][1] = r1;
                bf[jj * 2 + 1][0] = r2; bf[jj * 2 + 1][1] = r3;
            }
#pragma unroll
            for (int i = 0; i < 4; i++)
#pragma unroll
                for (int j = 0; j < 4; j++)
                    MMA_F16(acc[i * 4 + j], af[i][0], af[i][1], af[i][2], af[i][3],
                            bf[j][0], bf[j][1]);
        }
    };

    // 4-stage prologue: 3 chunks in flight
    issue_stage(0);
    if (nch > 1) issue_stage(1);
    else asm volatile("cp.async.commit_group;" ::: "memory");
    if (nch > 2) issue_stage(2);
    else asm volatile("cp.async.commit_group;" ::: "memory");
    for (int c = 0; c < nch; c++) {
        asm volatile("cp.async.wait_group 2;" ::: "memory");
        __syncthreads();
        if (c + 3 < nch) issue_stage(c + 3);
        else asm volatile("cp.async.commit_group;" ::: "memory");
        compute(c & 3);
    }

    int g = lane >> 2, q4 = lane & 3;

    if (MODE == 0 || MODE == 1 || MODE == 5) {
#pragma unroll
        for (int i = 0; i < 4; i++) {
#pragma unroll
            for (int j = 0; j < 4; j++) {
                int col = n0 + wn * 32 + j * 8 + q4 * 2;
                float b0 = bias[col], b1 = bias[col + 1];
                const float* a4 = acc[i * 4 + j];
#pragma unroll
                for (int half = 0; half < 2; half++) {
                    int mrow = m0 + wm * 64 + i * 16 + g + half * 8;
                    if (mrow >= M) continue;
                    float v0 = a4[half * 2 + 0] + b0;
                    float v1 = a4[half * 2 + 1] + b1;
                    if (MODE == 1) {
                        v0 = fast_gelu(v0);
                        v1 = fast_gelu(v1);
                    }
                    if (MODE == 1 || MODE == 5)
                        *(__half2*)(C16 + (size_t)mrow * Nn + col) = __floats2half2_rn(v0, v1);
                    else
                        *(float2*)(C + (size_t)mrow * Nn + col) = make_float2(v0, v1);
                }
            }
        }
    } else {
        asm volatile("cp.async.wait_group 0;" ::: "memory");
        __syncthreads();
        float* sv = sm;
#pragma unroll
        for (int i = 0; i < 4; i++) {
#pragma unroll
            for (int j = 0; j < 4; j++) {
                int col = wn * 32 + j * 8 + q4 * 2;
                float b0 = bias[col], b1 = bias[col + 1];
                const float* a4 = acc[i * 4 + j];
#pragma unroll
                for (int half = 0; half < 2; half++) {
                    int lr = wm * 64 + i * 16 + g + half * 8;
                    sv[lr * 264 + col]     = a4[half * 2 + 0] + b0;
                    sv[lr * 264 + col + 1] = a4[half * 2 + 1] + b1;
                }
            }
        }
        __syncthreads();
        int lr0 = wid * 8;
#pragma unroll
        for (int rr = 0; rr < 8; rr++) {
            int lr = lr0 + rr;
            size_t m = (size_t)m0 + lr;
            float vals[8];
            if (MODE == 3) {
                int b = (int)(m / Nrows), n = (int)(m % Nrows);
                float ha = d_hasany[b] ? 1.f : 0.f;
#pragma unroll
                for (int jj = 0; jj < 8; jj++) {
                    int e = lane + 32 * jj;
                    vals[jj] = res[(size_t)n * 256 + e] + ha * sv[lr * 264 + e];
                }
            } else {
#pragma unroll
                for (int jj = 0; jj < 8; jj++) {
                    int e = lane + 32 * jj;
                    vals[jj] = sv[lr * 264 + e] + __half2float(res16[m * 256 + e]);
                }
            }
            float sum = 0.f;
#pragma unroll
            for (int jj = 0; jj < 8; jj++) sum += vals[jj];
#pragma unroll
            for (int o = 16; o; o >>= 1) sum += __shfl_xor_sync(0xffffffffu, sum, o);
            float mu = sum * (1.f / 256.f);
            float s2 = 0.f;
#pragma unroll
            for (int jj = 0; jj < 8; jj++) { float dd = vals[jj] - mu; s2 += dd * dd; }
#pragma unroll
            for (int o = 16; o; o >>= 1) s2 += __shfl_xor_sync(0xffffffffu, s2, o);
            float rs = rsqrtf(s2 * (1.f / 256.f) + 1e-5f);
#pragma unroll
            for (int jj = 0; jj < 8; jj++) {
                int e = lane + 32 * jj;
                float ov = (vals[jj] - mu) * rs * lg[e] + lb[e];
                if (MODE == 3) C16[m * 256 + e] = __float2half(ov);
                else           C[m * 256 + e] = ov;
            }
        }
    }
}

// ---------------- k/v projection + segment scan (merged) ------------------------
__global__ void kv_kernel(const float* __restrict__ Hg, const int* __restrict__ idx,
                          const float* __restrict__ ipw, const float* __restrict__ ipb,
                          const int* __restrict__ ba, int P, int B) {
    __shared__ float hrow[Dd];
    int p = blockIdx.x, t = threadIdx.x;
    if (p == 0 && t == 0) {
        for (int b = 0; b < B; b++) {
            int s = P, e = 0;
            for (int pp = 0; pp < P; pp++)
                if (ba[pp] == b) { if (pp < s) s = pp; e = pp + 1; }
            if (e > s) { d_segs[2*b] = s; d_segs[2*b+1] = e; d_hasany[b] = 1; }
            else       { d_segs[2*b] = 0; d_segs[2*b+1] = 0; d_hasany[b] = 0; }
        }
    }
    hrow[t] = Hg[(size_t)idx[p] * Dd + t];
    __syncthreads();
    const float4* h4 = (const float4*)hrow;
    const float4* wk = (const float4*)(ipw + (size_t)(Dd + t) * Dd);
    const float4* wv = (const float4*)(ipw + (size_t)(2 * Dd + t) * Dd);
    float ak = ipb[Dd + t], av = ipb[2 * Dd + t];
#pragma unroll 16
    for (int c = 0; c < Dd / 4; c++) {
        float4 hv = h4[c]; float4 a = wk[c]; float4 b = wv[c];
        ak += hv.x*a.x + hv.y*a.y + hv.z*a.z + hv.w*a.w;
        av += hv.x*b.x + hv.y*b.y + hv.z*b.z + hv.w*b.w;
    }
    d_k16[p * Dd + t] = __float2half(ak);
    d_v[p * Dd + t]   = av;
}

// ---------------- tensor-core scores: C_h[n,p] = scale * q_h @ k_h^T -----------
// grid (ceil(N/128), 8 heads); block 256 = 8 warps, warp tile 16n x 128p
__global__ __launch_bounds__(256, 1) void scores_mma(int N) {
    __shared__ __align__(128) char smem[32768];  // q 16KB | k 16KB, 128B rows
    uint32_t sbase = smem_u32(smem);
    int h = blockIdx.y;
    int n0 = blockIdx.x * 128;
    int tid = threadIdx.x, wid = tid >> 5, lane = tid & 31;

    // load q/k tiles (64B of data per 128B row, swizzled)
#pragma unroll
    for (int j = 0; j < 2; j++) {
        int seg = tid + j * 256;
        int r = seg >> 2, kk = seg & 3;
        uint32_t off = ((uint32_t)(r * 128 + kk * 16)) ^ ((uint32_t)(r & 7) << 4);
        const __half* gq = d_q16 + (size_t)((n0 + r < N) ? n0 + r : 0) * Dd + h * DHh + kk * 8;
        int szq = (n0 + r < N) ? 16 : 0;
        asm volatile("cp.async.cg.shared.global [%0], [%1], 16, %2;"
                     :: "r"(sbase + off), "l"(gq), "r"(szq));
        const __half* gk = d_k16 + (size_t)r * Dd + h * DHh + kk * 8;
        asm volatile("cp.async.cg.shared.global [%0], [%1], 16;"
                     :: "r"(sbase + 16384u + off), "l"(gk));
    }
    asm volatile("cp.async.commit_group;" ::: "memory");
    asm volatile("cp.async.wait_group 0;" ::: "memory");
    __syncthreads();

    int a_mloc = lane & 15;
    int a_kb   = (lane >> 4) << 4;
    int b_nloc = (((lane >> 4) & 1) << 3) + (lane & 7);
    int b_kb   = ((lane >> 3) & 1) << 4;

    float acc[16][4] = {};
#pragma unroll
    for (int ks = 0; ks < 2; ks++) {
        int kb = ks * 32;
        uint32_t a0, a1, a2, a3;
        {
            int row = wid * 16 + a_mloc;
            uint32_t off = ((uint32_t)(row * 128 + kb + a_kb)) ^ ((uint32_t)(row & 7) << 4);
            LDSM4(a0, a1, a2, a3, sbase + off);
        }
#pragma unroll
        for (int jj = 0; jj < 8; jj++) {
            int row = jj * 16 + b_nloc;
            uint32_t off = ((uint32_t)(row * 128 + kb + b_kb)) ^ ((uint32_t)(row & 7) << 4);
            uint32_t r0, r1, r2, r3;
            LDSM4(r0, r1, r2, r3, sbase + 16384u + off);
            MMA_F16(acc[jj * 2 + 0], a0, a1, a2, a3, r0, r1);
            MMA_F16(acc[jj * 2 + 1], a0, a1, a2, a3, r2, r3);
        }
    }

    const float scale = 0.17677669529663687f;  // 1/sqrt(32)
    int g = lane >> 2, q4 = lane & 3;
#pragma unroll
    for (int j = 0; j < 16; j++) {
        int col = j * 8 + q4 * 2;
#pragma unroll
        for (int half = 0; half < 2; half++) {
            int n = n0 + wid * 16 + g + half * 8;
            if (n >= N) continue;
            float* sp = d_scores + ((size_t)n * Hh + h) * Pmax + col;
            *(float2*)sp = make_float2(acc[j][half * 2] * scale,
                                       acc[j][half * 2 + 1] * scale);
        }
    }
}

// ---------------- segment softmax + ctx accumulation (fp16 out) ----------------
__global__ void attn_kernel(int N) {
    int b = blockIdx.y;
    int h = threadIdx.x >> 5, l = threadIdx.x & 31;
    int s = d_segs[2 * b], e = d_segs[2 * b + 1];
    int L = e - s;
    __shared__ float ws[8][128];
    int nEnd = min(N, (int)(blockIdx.x + 1) * 16);
    for (int n = blockIdx.x * 16; n < nEnd; n++) {
        size_t obase = ((size_t)b * N + n) * Dd + h * DHh;
        if (L <= 0) { d_ctx16[obase + l] = __float2half(0.f); continue; }
        float sc[4]; int cnt = 0;
        float m = -1e30f;
        for (int pl = l; pl < L; pl += 32) {
            float xv = d_scores[((size_t)n * Hh + h) * Pmax + s + pl];
            sc[cnt++] = xv;
            m = fmaxf(m, xv);
        }
#pragma unroll
        for (int o = 16; o; o >>= 1) m = fmaxf(m, __shfl_xor_sync(0xffffffffu, m, o));
        float sum = 0.f; cnt = 0;
        for (int pl = l; pl < L; pl += 32) {
            float w = __expf(sc[cnt++] - m);
            ws[h][pl] = w;
            sum += w;
        }
#pragma unroll
        for (int o = 16; o; o >>= 1) sum += __shfl_xor_sync(0xffffffffu, sum, o);
        float inv = 1.f / sum;
        __syncwarp();
        float acc = 0.f;
        for (int pl = 0; pl < L; pl++)
            acc += ws[h][pl] * d_v[(size_t)(s + pl) * Dd + h * DHh + l];
        d_ctx16[obase + l] = __float2half(acc * inv);
        __syncwarp();
    }
}

// -------------------------------- launch ---------------------------------------
extern "C" void kernel_launch(void* const* d_in, const int* in_sizes, int n_in,
                              void* d_out, int out_size) {
    const float* Hg  = (const float*)d_in[0];
    const int*  pidx = (const int*)d_in[1];
    const int*  ba   = (const int*)d_in[2];
    const float* ipw = (const float*)d_in[4];
    const float* ipb = (const float*)d_in[5];
    const float* opw = (const float*)d_in[6];
    const float* opb = (const float*)d_in[7];
    const float* w1  = (const float*)d_in[8];
    const float* b1  = (const float*)d_in[9];
    const float* w2  = (const float*)d_in[10];
    const float* b2  = (const float*)d_in[11];
    const float* g1  = (const float*)d_in[12];
    const float* be1 = (const float*)d_in[13];
    const float* g2  = (const float*)d_in[14];
    const float* be2 = (const float*)d_in[15];
    float* out = (float*)d_out;

    int N = in_sizes[0] / Dd;          // 6000
    int P = in_sizes[1];               // 128
    int B = out_size / (N * Dd);       // 16
    int M = B * N;                     // 96000

    __half *hg16, *wq16, *wo16, *w116, *w216, *x16, *ctx16, *hidden16, *q16;
    cudaGetSymbolAddress((void**)&q16,      d_q16);
    cudaGetSymbolAddress((void**)&hg16,     d_hg16);
    cudaGetSymbolAddress((void**)&wq16,     d_wq16);
    cudaGetSymbolAddress((void**)&wo16,     d_wo16);
    cudaGetSymbolAddress((void**)&w116,     d_w116);
    cudaGetSymbolAddress((void**)&w216,     d_w216);
    cudaGetSymbolAddress((void**)&x16,      d_x16);
    cudaGetSymbolAddress((void**)&ctx16,    d_ctx16);
    cudaGetSymbolAddress((void**)&hidden16, d_hidden16);

    cudaFuncSetAttribute((tgemm<5, 256>),  cudaFuncAttributeMaxDynamicSharedMemorySize, SMEM_SZ);
    cudaFuncSetAttribute((tgemm<1, 256>),  cudaFuncAttributeMaxDynamicSharedMemorySize, SMEM_SZ);
    cudaFuncSetAttribute((tgemm<3, 256>),  cudaFuncAttributeMaxDynamicSharedMemorySize, SMEM_SZ);
    cudaFuncSetAttribute((tgemm<4, 1024>), cudaFuncAttributeMaxDynamicSharedMemorySize, SMEM_SZ);

    int tot4 = HG4 + 2 * WQ4 + 2 * W14;
    // 1. single fused fp16 conversion
    f2h_all<<<(tot4 + 255) / 256, 256>>>(Hg, ipw, opw, w1, w2);
    // 2. k/v projections (k16) + batch segments
    kv_kernel<<<P, Dd>>>(Hg, pidx, ipw, ipb, ba, P, B);
    // 3. q16 = fp16(H @ Wq^T + bq)
    tgemm<5, 256><<<dim3(1, (N + 127) / 128), 512, SMEM_SZ>>>(
        hg16, wq16, ipb, nullptr, nullptr, nullptr, q16, nullptr, nullptr, N, Dd, N);
    // 4. tensor-core scores (shared across batches)
    scores_mma<<<dim3((N + 127) / 128, Hh), 256>>>(N);
    // 5. segment softmax + ctx (fp16 out)
    attn_kernel<<<dim3((N + 15) / 16, B), 256>>>(N);
    // 6. x16 = LN1(H + has_any*(ctx @ Wout^T + bout))
    tgemm<3, 256><<<dim3(1, M / 128), 512, SMEM_SZ>>>(
        ctx16, wo16, opb, Hg, nullptr, nullptr, x16, g1, be1, M, Dd, N);
    // 7. hidden = fast_gelu(x @ W1^T + b1) -> fp16
    tgemm<1, 256><<<dim3(FF / 256, M / 128), 512, SMEM_SZ>>>(
        x16, w116, b1, nullptr, nullptr, nullptr, hidden16, nullptr, nullptr, M, FF, N);
    // 8. out = LN2(x16 + hidden @ W2^T + b2)
    tgemm<4, 1024><<<dim3(1, M / 128), 512, SMEM_SZ>>>(
        hidden16, w216, b2, nullptr, x16, out, nullptr, g2, be2, M, Dd, N);
}